// round 1
// baseline (speedup 1.0000x reference)
#include <cuda_runtime.h>
#include <math.h>

#define NPTS 4096
#define NB 8
#define KNN 32
#define ROWS_TOTAL (NB*NPTS)   // 32768

// ---------------- scratch (device globals; no allocation) ----------------
__device__ float g_D[(size_t)NB*NPTS*NPTS];   // 512 MB dist matrix
__device__ float g_x[ROWS_TOTAL*64];          // current features
__device__ float g_sq[ROWS_TOTAL];            // row squared norms
__device__ float g_q[ROWS_TOTAL*64];          // constant part per edgeconv
__device__ float g_v[ROWS_TOTAL*64];          // neighbor part per edgeconv
__device__ float g_y[ROWS_TOTAL*64];          // edgeconv output (pre ReLU+BN)
__device__ float g_scale[64];
__device__ float g_shift[64];
__device__ float g_part[256*64];
__device__ float g_partsq[256*64];
__device__ float g_lpart[96];

// ---------------- layer-1 prep: q,v,sq from raw x (f=3) ----------------
__global__ __launch_bounds__(128) void prep1_kernel(
    const float* __restrict__ x, const float* __restrict__ W,
    const float* __restrict__ b)
{
    __shared__ float sW[6*64];
    __shared__ float sb[64];
    int t = threadIdx.x;
    for (int i = t; i < 6*64; i += 128) sW[i] = W[i];
    if (t < 64) sb[t] = b[t];
    __syncthreads();
    int row = blockIdx.x * 128 + t;
    float x0 = x[row*3+0], x1 = x[row*3+1], x2 = x[row*3+2];
    g_sq[row] = x0*x0 + x1*x1 + x2*x2;
    #pragma unroll 4
    for (int o = 0; o < 64; o++) {
        float s1 = x0*sW[0*64+o] + x1*sW[1*64+o] + x2*sW[2*64+o];
        float s2 = x0*sW[3*64+o] + x1*sW[4*64+o] + x2*sW[5*64+o];
        g_q[row*64+o] = s1 - s2 + sb[o];
        g_v[row*64+o] = s2;
    }
}

// ------- layers 2/3 prep: apply ReLU+BN to y, write x,sq,q,v (f=64) -------
template<int O>
__global__ __launch_bounds__(128) void prepbn_kernel(
    const float* __restrict__ W, const float* __restrict__ b)
{
    __shared__ float sW[128*O];
    __shared__ float sb[O];
    __shared__ float ssc[64], ssh[64];
    int t = threadIdx.x;
    for (int i = t; i < 128*O; i += 128) sW[i] = W[i];
    if (t < O) sb[t] = b[t];
    if (t < 64) { ssc[t] = g_scale[t]; ssh[t] = g_shift[t]; }
    __syncthreads();
    int row = blockIdx.x * 128 + t;
    float xr[64];
    float s = 0.f;
    #pragma unroll
    for (int f = 0; f < 64; f++) {
        float yy = g_y[(size_t)row*64 + f];
        float xn = ssc[f]*fmaxf(yy, 0.f) + ssh[f];
        xr[f] = xn;
        s += xn*xn;
        g_x[(size_t)row*64 + f] = xn;
    }
    g_sq[row] = s;
    #pragma unroll 2
    for (int o = 0; o < O; o++) {
        float s1 = 0.f, s2 = 0.f;
        #pragma unroll
        for (int f = 0; f < 64; f++) {
            s1 += xr[f]*sW[f*O + o];
            s2 += xr[f]*sW[(64+f)*O + o];
        }
        g_q[(size_t)row*O + o] = s1 - s2 + sb[o];
        g_v[(size_t)row*O + o] = s2;
    }
}

// ---------------- distance matrix: D = sq_i + sq_j - 2 X X^T ----------------
__global__ __launch_bounds__(256) void dist_kernel(const float* __restrict__ X, int f)
{
    int bz = blockIdx.z;
    const float* Xb = X + (size_t)bz*NPTS*f;
    const float* sqb = g_sq + bz*NPTS;
    float* Db = g_D + (size_t)bz*NPTS*NPTS;
    int i0 = blockIdx.y*128, j0 = blockIdx.x*128;
    __shared__ float As[32][129];
    __shared__ float Bs[32][129];
    int tid = threadIdx.x;
    int tx = tid & 15, ty = tid >> 4;
    float acc[8][8];
    #pragma unroll
    for (int a = 0; a < 8; a++)
        #pragma unroll
        for (int bb = 0; bb < 8; bb++) acc[a][bb] = 0.f;

    for (int kc = 0; kc < f; kc += 32) {
        for (int tdx = tid; tdx < 128*32; tdx += 256) {
            int r = tdx >> 5, c = tdx & 31;
            float av = (kc + c < f) ? Xb[(size_t)(i0+r)*f + kc + c] : 0.f;
            float bv = (kc + c < f) ? Xb[(size_t)(j0+r)*f + kc + c] : 0.f;
            As[c][r] = av;
            Bs[c][r] = bv;
        }
        __syncthreads();
        int kend = f - kc; if (kend > 32) kend = 32;
        for (int k = 0; k < kend; k++) {
            float a[8], bv[8];
            #pragma unroll
            for (int u = 0; u < 8; u++) a[u]  = As[k][ty*8 + u];
            #pragma unroll
            for (int u = 0; u < 8; u++) bv[u] = Bs[k][tx*8 + u];
            #pragma unroll
            for (int ui = 0; ui < 8; ui++)
                #pragma unroll
                for (int uj = 0; uj < 8; uj++)
                    acc[ui][uj] += a[ui]*bv[uj];
        }
        __syncthreads();
    }
    #pragma unroll
    for (int ui = 0; ui < 8; ui++) {
        int i = i0 + ty*8 + ui;
        float si = sqb[i];
        #pragma unroll
        for (int uj = 0; uj < 8; uj++) {
            int j = j0 + tx*8 + uj;
            Db[(size_t)i*NPTS + j] = si + sqb[j] - 2.f*acc[ui][uj];
        }
    }
}

// ---------- per-row exact top-K (radix select) + gather-max of v ----------
__device__ __forceinline__ unsigned ordf(float f) {
    unsigned u = __float_as_uint(f);
    return (u & 0x80000000u) ? ~u : (u | 0x80000000u);
}

__global__ __launch_bounds__(256) void knnagg_kernel(float* __restrict__ out, int O)
{
    __shared__ unsigned su[NPTS];
    __shared__ unsigned s_hist[256];
    __shared__ int s_sel[KNN];
    __shared__ int s_tie[64];
    __shared__ int s_nsel, s_ntie, s_rem;
    __shared__ unsigned s_prefix;
    __shared__ float s_pm[4][64];

    int gi = blockIdx.x;
    int b = gi >> 12;
    int i = gi & 4095;
    const float* Drow = g_D + (size_t)b*NPTS*NPTS + (size_t)i*NPTS;
    int t = threadIdx.x;

    for (int j = t; j < NPTS; j += 256) su[j] = ordf(Drow[j]);
    if (t == 0) { s_rem = KNN; s_prefix = 0; s_nsel = 0; s_ntie = 0; }
    __syncthreads();

    // 4-pass radix select: find value of the 32nd smallest + rank-within-ties
    for (int pass = 0; pass < 4; pass++) {
        int shift = 24 - 8*pass;
        s_hist[t] = 0;
        __syncthreads();
        unsigned pfx = s_prefix;
        for (int j = t; j < NPTS; j += 256) {
            unsigned u = su[j];
            bool m = (pass == 0) || (((u ^ pfx) >> (shift + 8)) == 0);
            if (m) atomicAdd(&s_hist[(u >> shift) & 0xFF], 1u);
        }
        __syncthreads();
        // inclusive scan over 256 bins
        for (int off = 1; off < 256; off <<= 1) {
            unsigned vv = (t >= off) ? s_hist[t - off] : 0u;
            __syncthreads();
            s_hist[t] += vv;
            __syncthreads();
        }
        int rem = s_rem;
        unsigned incl = s_hist[t];
        unsigned excl = (t > 0) ? s_hist[t-1] : 0u;
        __syncthreads();
        if ((int)excl < rem && rem <= (int)incl) {
            s_prefix = pfx | ((unsigned)t << shift);
            s_rem = rem - (int)excl;
        }
        __syncthreads();
    }
    unsigned T = s_prefix;
    int need = s_rem;

    // gather strictly-smaller + ties (lowest-index tie break, matching top_k)
    for (int j = t; j < NPTS; j += 256) {
        unsigned u = su[j];
        if (u < T) {
            int p = atomicAdd(&s_nsel, 1);
            if (p < KNN) s_sel[p] = j;
        } else if (u == T) {
            int p = atomicAdd(&s_ntie, 1);
            if (p < 64) s_tie[p] = j;
        }
    }
    __syncthreads();
    if (t == 0) {
        int nt = s_ntie; if (nt > 64) nt = 64;
        for (int a = 1; a < nt; a++) {           // tiny insertion sort
            int key = s_tie[a]; int c2 = a - 1;
            while (c2 >= 0 && s_tie[c2] > key) { s_tie[c2+1] = s_tie[c2]; c2--; }
            s_tie[c2+1] = key;
        }
        int base = s_nsel;
        int takes = (need < nt) ? need : nt;
        for (int a = 0; a < takes; a++) s_sel[base + a] = s_tie[a];
        s_nsel = base + takes;
    }
    __syncthreads();

    int nsel = s_nsel;
    int c = t & 63, g = t >> 6;
    float m = -INFINITY;
    if (c < O) {
        for (int s = g; s < nsel; s += 4)
            m = fmaxf(m, g_v[((size_t)(b*NPTS) + s_sel[s])*O + c]);
    }
    s_pm[g][c] = m;
    __syncthreads();
    if (t < O) {
        float mm = fmaxf(fmaxf(s_pm[0][t], s_pm[1][t]),
                         fmaxf(s_pm[2][t], s_pm[3][t]));
        out[(size_t)gi*O + t] = g_q[(size_t)gi*O + t] + mm;
    }
}

// ---------------- BN stats: partial sums over ReLU(y) ----------------
__global__ __launch_bounds__(256) void bnred_kernel()
{
    __shared__ float ps[256], pss[256];
    int t = threadIdx.x, c = t & 63, g = t >> 6;
    int row0 = blockIdx.x * 128;
    float s = 0.f, ss = 0.f;
    for (int r = g; r < 128; r += 4) {
        float a = fmaxf(g_y[(size_t)(row0+r)*64 + c], 0.f);
        s += a; ss += a*a;
    }
    ps[t] = s; pss[t] = ss;
    __syncthreads();
    if (t < 64) {
        float S  = ps[t]  + ps[t+64]  + ps[t+128]  + ps[t+192];
        float SS = pss[t] + pss[t+64] + pss[t+128] + pss[t+192];
        g_part[blockIdx.x*64 + t] = S;
        g_partsq[blockIdx.x*64 + t] = SS;
    }
}

__global__ __launch_bounds__(64) void bnfin_kernel(
    const float* __restrict__ gamma, const float* __restrict__ beta)
{
    int c = threadIdx.x;
    float s = 0.f, ss = 0.f;
    for (int p = 0; p < 256; p++) { s += g_part[p*64 + c]; ss += g_partsq[p*64 + c]; }
    const float inv = 1.f / 32768.f;
    float mean = s * inv;
    float var = ss * inv - mean*mean;
    if (var < 0.f) var = 0.f;
    float sc = gamma[c] * rsqrtf(var + 1e-5f);
    g_scale[c] = sc;
    g_shift[c] = beta[c] - mean*sc;
}

// ---------------- loss = mean((h - target)^2) ----------------
__global__ __launch_bounds__(256) void lossred_kernel(
    const float* __restrict__ h, const float* __restrict__ tgt)
{
    __shared__ float ps[256];
    int t = threadIdx.x;
    int base = blockIdx.x * 1024;
    float s = 0.f;
    for (int k = t; k < 1024; k += 256) {
        float d = h[base + k] - tgt[base + k];
        s += d*d;
    }
    ps[t] = s; __syncthreads();
    for (int off = 128; off > 0; off >>= 1) {
        if (t < off) ps[t] += ps[t + off];
        __syncthreads();
    }
    if (t == 0) g_lpart[blockIdx.x] = ps[0];
}

__global__ __launch_bounds__(128) void lossfin_kernel(float* __restrict__ out_loss)
{
    __shared__ float buf[128];
    int t = threadIdx.x;
    buf[t] = (t < 96) ? g_lpart[t] : 0.f;
    __syncthreads();
    for (int off = 64; off > 0; off >>= 1) {
        if (t < off) buf[t] += buf[t + off];
        __syncthreads();
    }
    if (t == 0) *out_loss = buf[0] / 98304.0f;
}

// ---------------- driver ----------------
extern "C" void kernel_launch(void* const* d_in, const int* in_sizes, int n_in,
                              void* d_out, int out_size)
{
    const float* x   = (const float*)d_in[0];
    const float* tgt = (const float*)d_in[1];
    const float* W1  = (const float*)d_in[2];
    const float* b1  = (const float*)d_in[3];
    const float* g1  = (const float*)d_in[4];
    const float* be1 = (const float*)d_in[5];
    const float* W2  = (const float*)d_in[6];
    const float* b2  = (const float*)d_in[7];
    const float* g2  = (const float*)d_in[8];
    const float* be2 = (const float*)d_in[9];
    const float* W3  = (const float*)d_in[10];
    const float* b3  = (const float*)d_in[11];
    float* out = (float*)d_out;

    float* p_y = nullptr;
    float* p_xg = nullptr;
    cudaGetSymbolAddress((void**)&p_y, g_y);
    cudaGetSymbolAddress((void**)&p_xg, g_x);

    dim3 dgrid(32, 32, NB);

    // ----- layer 1 (f=3 -> 64) -----
    prep1_kernel<<<256, 128>>>(x, W1, b1);
    dist_kernel<<<dgrid, 256>>>(x, 3);
    knnagg_kernel<<<ROWS_TOTAL, 256>>>(p_y, 64);
    bnred_kernel<<<256, 256>>>();
    bnfin_kernel<<<1, 64>>>(g1, be1);

    // ----- layer 2 (f=64 -> 64) -----
    prepbn_kernel<64><<<256, 128>>>(W2, b2);
    dist_kernel<<<dgrid, 256>>>(p_xg, 64);
    knnagg_kernel<<<ROWS_TOTAL, 256>>>(p_y, 64);
    bnred_kernel<<<256, 256>>>();
    bnfin_kernel<<<1, 64>>>(g2, be2);

    // ----- layer 3 (f=64 -> 3), writes h directly to d_out -----
    prepbn_kernel<3><<<256, 128>>>(W3, b3);
    dist_kernel<<<dgrid, 256>>>(p_xg, 64);
    knnagg_kernel<<<ROWS_TOTAL, 256>>>(out, 3);

    // ----- loss -----
    lossred_kernel<<<96, 256>>>(out, tgt);
    lossfin_kernel<<<1, 128>>>(out + (out_size - 1));
}

// round 2
// speedup vs baseline: 1.5953x; 1.5953x over previous
#include <cuda_runtime.h>
#include <math.h>
#include <stdint.h>

#define NPTS 4096
#define NB 8
#define KNN 32
#define ROWS_TOTAL (NB*NPTS)   // 32768
#define FULLMASK 0xffffffffu

// ---------------- scratch (device globals; no allocation) ----------------
__device__ float g_xT[(size_t)NB*64*NPTS];    // transposed features [b][f][n] (8MB)
__device__ float g_sq[ROWS_TOTAL];            // row squared norms
__device__ float g_q[ROWS_TOTAL*64];          // constant part per edgeconv
__device__ float g_v[ROWS_TOTAL*64];          // neighbor part per edgeconv
__device__ float g_y[ROWS_TOTAL*64];          // edgeconv output (pre ReLU+BN)
__device__ float g_scale[64];
__device__ float g_shift[64];
__device__ float g_part[256*64];
__device__ float g_partsq[256*64];
__device__ float g_lpart[96];

// packed f32x2 fma (sm_100+): 2 FMAs per instruction -> full fp32 rate
__device__ __forceinline__ unsigned long long ffma2(
    unsigned long long a, unsigned long long b, unsigned long long c)
{
    unsigned long long d;
    asm("fma.rn.f32x2 %0, %1, %2, %3;" : "=l"(d) : "l"(a), "l"(b), "l"(c));
    return d;
}

__device__ __forceinline__ unsigned ordf(float f) {
    unsigned u = __float_as_uint(f);
    return u ^ (unsigned)(((int)u >> 31) | 0x80000000);
}

// ---------------- layer-1 prep: xT,q,v,sq from raw x (f=3) ----------------
__global__ __launch_bounds__(128) void prep1_kernel(
    const float* __restrict__ x, const float* __restrict__ W,
    const float* __restrict__ b)
{
    __shared__ float sW[6*64];
    __shared__ float sb[64];
    int t = threadIdx.x;
    for (int i = t; i < 6*64; i += 128) sW[i] = W[i];
    if (t < 64) sb[t] = b[t];
    __syncthreads();
    int row = blockIdx.x * 128 + t;
    int bt = row >> 12, n = row & 4095;
    float x0 = x[row*3+0], x1 = x[row*3+1], x2 = x[row*3+2];
    g_sq[row] = x0*x0 + x1*x1 + x2*x2;
    g_xT[((size_t)bt*3 + 0)*NPTS + n] = x0;
    g_xT[((size_t)bt*3 + 1)*NPTS + n] = x1;
    g_xT[((size_t)bt*3 + 2)*NPTS + n] = x2;
    #pragma unroll 4
    for (int o = 0; o < 64; o++) {
        float s1 = x0*sW[0*64+o] + x1*sW[1*64+o] + x2*sW[2*64+o];
        float s2 = x0*sW[3*64+o] + x1*sW[4*64+o] + x2*sW[5*64+o];
        g_q[row*64+o] = s1 - s2 + sb[o];
        g_v[row*64+o] = s2;
    }
}

// ------- layers 2/3 prep: ReLU+BN on y -> xT, sq, q, v (f=64) -------
template<int O>
__global__ __launch_bounds__(128) void prepbn_kernel(
    const float* __restrict__ W, const float* __restrict__ b)
{
    __shared__ float sW[128*O];
    __shared__ float sb[O];
    __shared__ float ssc[64], ssh[64];
    int t = threadIdx.x;
    for (int i = t; i < 128*O; i += 128) sW[i] = W[i];
    if (t < O) sb[t] = b[t];
    if (t < 64) { ssc[t] = g_scale[t]; ssh[t] = g_shift[t]; }
    __syncthreads();
    int row = blockIdx.x * 128 + t;
    int bt = row >> 12, n = row & 4095;
    float xr[64];
    float s = 0.f;
    #pragma unroll
    for (int f = 0; f < 64; f++) {
        float yy = g_y[(size_t)row*64 + f];
        float xn = ssc[f]*fmaxf(yy, 0.f) + ssh[f];
        xr[f] = xn;
        s += xn*xn;
        g_xT[((size_t)bt*64 + f)*NPTS + n] = xn;
    }
    g_sq[row] = s;
    #pragma unroll 2
    for (int o = 0; o < O; o++) {
        float s1 = 0.f, s2 = 0.f;
        #pragma unroll
        for (int f = 0; f < 64; f++) {
            s1 += xr[f]*sW[f*O + o];
            s2 += xr[f]*sW[(64+f)*O + o];
        }
        g_q[(size_t)row*O + o] = s1 - s2 + sb[o];
        g_v[(size_t)row*O + o] = s2;
    }
}

// ============= fused: dist + exact top-32 stream-select + v-gather =============
// Block: 256 threads = 8 warps; each warp owns 8 rows i; block = 64 rows.
// j streamed in chunks of 128 staged in smem (per-f xor-swizzled chunks).
// Ranking key = sq_j - 2*dot(x_i,x_j)  (monotone with true dist per row).
template<int F, int O>
__global__ __launch_bounds__(256, 2) void fused_knn_kernel(
    const float* __restrict__ XT, const float* __restrict__ SQ,
    const float* __restrict__ V, const float* __restrict__ Q,
    float* __restrict__ OUT)
{
    extern __shared__ float sm[];
    float* s_xj  = sm;                 // F*128 floats, swizzled
    float* s_xi2 = sm + F*128;         // F*64 float2 = (-2 x_i, -2 x_i), [f][i]
    float* s_sqj = sm + 2*F*128;       // 128

    const int t = threadIdx.x;
    const int lane = t & 31;
    const int w = t >> 5;
    const int wrow = w * 8;
    const int rowbase = blockIdx.x * 64;
    const int batch = rowbase >> 12;
    const int nbase = rowbase & 4095;
    const float* XTb = XT + (size_t)batch * F * NPTS;
    const float* SQb = SQ + batch * NPTS;

    // build xi2 tile once: packed duplicated (-2*x_i)
    for (int idx = t; idx < F*64; idx += 256) {
        int f = idx >> 6, i = idx & 63;
        float s = -2.0f * XTb[(size_t)f * NPTS + nbase + i];
        ((float2*)s_xi2)[f*64 + i] = make_float2(s, s);
    }

    unsigned long long acc0[8], acc1[8];
    unsigned sval[8]; int sidx[8]; unsigned thr[8]; int thrlane[8];
    #pragma unroll
    for (int i = 0; i < 8; i++) {
        sval[i] = 0xFFFFFFFFu; sidx[i] = 0;
        thr[i] = 0xFFFFFFFFu;  thrlane[i] = 0;
    }

    for (int jb = 0; jb < NPTS; jb += 128) {
        __syncthreads();
        if (t < 128) s_sqj[t] = SQb[jb + t];
        if (F == 64) {
            #pragma unroll
            for (int f = w; f < 64; f += 8) {
                float4 vv = *(const float4*)&XTb[(size_t)f * NPTS + jb + 4*lane];
                int cp = lane ^ (f & 31);
                *(float4*)&s_xj[f*128 + 4*cp] = vv;
            }
        } else {
            for (int idx = t; idx < F*128; idx += 256) {
                int f = idx >> 7, jj = idx & 127;
                float vv = XTb[(size_t)f * NPTS + jb + jj];
                int cp = (jj >> 2) ^ (f & 31);
                s_xj[f*128 + 4*cp + (jj & 3)] = vv;
            }
        }
        __syncthreads();

        unsigned long long sq01 = *(const unsigned long long*)&s_sqj[4*lane];
        unsigned long long sq23 = *(const unsigned long long*)&s_sqj[4*lane + 2];
        #pragma unroll
        for (int i = 0; i < 8; i++) { acc0[i] = sq01; acc1[i] = sq23; }

        #pragma unroll 8
        for (int f = 0; f < F; f++) {
            const float* xr = s_xj + f*128 + 4*(lane ^ (f & 31));
            unsigned long long xj01 = *(const unsigned long long*)xr;
            unsigned long long xj23 = *(const unsigned long long*)(xr + 2);
            const ulonglong2* xip =
                (const ulonglong2*)((const float2*)s_xi2 + f*64 + wrow);
            ulonglong2 q0 = xip[0], q1 = xip[1], q2 = xip[2], q3 = xip[3];
            acc0[0] = ffma2(q0.x, xj01, acc0[0]); acc1[0] = ffma2(q0.x, xj23, acc1[0]);
            acc0[1] = ffma2(q0.y, xj01, acc0[1]); acc1[1] = ffma2(q0.y, xj23, acc1[1]);
            acc0[2] = ffma2(q1.x, xj01, acc0[2]); acc1[2] = ffma2(q1.x, xj23, acc1[2]);
            acc0[3] = ffma2(q1.y, xj01, acc0[3]); acc1[3] = ffma2(q1.y, xj23, acc1[3]);
            acc0[4] = ffma2(q2.x, xj01, acc0[4]); acc1[4] = ffma2(q2.x, xj23, acc1[4]);
            acc0[5] = ffma2(q2.y, xj01, acc0[5]); acc1[5] = ffma2(q2.y, xj23, acc1[5]);
            acc0[6] = ffma2(q3.x, xj01, acc0[6]); acc1[6] = ffma2(q3.x, xj23, acc1[6]);
            acc0[7] = ffma2(q3.y, xj01, acc0[7]); acc1[7] = ffma2(q3.y, xj23, acc1[7]);
        }

        // exact streaming top-32 (ordf-u32 domain, REDUX threshold)
        #pragma unroll
        for (int i = 0; i < 8; i++) {
            float kf[4];
            kf[0] = __uint_as_float((unsigned)acc0[i]);
            kf[1] = __uint_as_float((unsigned)(acc0[i] >> 32));
            kf[2] = __uint_as_float((unsigned)acc1[i]);
            kf[3] = __uint_as_float((unsigned)(acc1[i] >> 32));
            #pragma unroll
            for (int jj = 0; jj < 4; jj++) {
                unsigned key = ordf(kf[jj]);
                unsigned m = __ballot_sync(FULLMASK, key < thr[i]);
                while (m) {
                    int src = __ffs(m) - 1; m &= m - 1;
                    unsigned kc = __shfl_sync(FULLMASK, key, src);
                    if (kc < thr[i]) {
                        if (lane == thrlane[i]) { sval[i] = kc; sidx[i] = jb + 4*src + jj; }
                        thr[i] = __reduce_max_sync(FULLMASK, sval[i]);
                        thrlane[i] = __ffs(__ballot_sync(FULLMASK, sval[i] == thr[i])) - 1;
                    }
                }
            }
        }
    }

    // v-gather-max + output
    const int bb = batch * NPTS;
    #pragma unroll
    for (int i = 0; i < 8; i++) {
        int row = rowbase + wrow + i;
        if (O == 64) {
            float m0 = -INFINITY, m1 = -INFINITY;
            #pragma unroll 4
            for (int s = 0; s < 32; s++) {
                int js = __shfl_sync(FULLMASK, sidx[i], s);
                const float* vp = V + (size_t)(bb + js) * 64;
                m0 = fmaxf(m0, vp[lane]);
                m1 = fmaxf(m1, vp[lane + 32]);
            }
            OUT[(size_t)row*64 + lane]      = Q[(size_t)row*64 + lane] + m0;
            OUT[(size_t)row*64 + lane + 32] = Q[(size_t)row*64 + lane + 32] + m1;
        } else {
            float m0 = -INFINITY;
            for (int s = 0; s < 32; s++) {
                int js = __shfl_sync(FULLMASK, sidx[i], s);
                if (lane < O) m0 = fmaxf(m0, V[(size_t)(bb + js) * O + lane]);
            }
            if (lane < O) OUT[(size_t)row*O + lane] = Q[(size_t)row*O + lane] + m0;
        }
    }
}

// ---------------- BN stats: partial sums over ReLU(y) ----------------
__global__ __launch_bounds__(256) void bnred_kernel()
{
    __shared__ float ps[256], pss[256];
    int t = threadIdx.x, c = t & 63, g = t >> 6;
    int row0 = blockIdx.x * 128;
    float s = 0.f, ss = 0.f;
    for (int r = g; r < 128; r += 4) {
        float a = fmaxf(g_y[(size_t)(row0+r)*64 + c], 0.f);
        s += a; ss += a*a;
    }
    ps[t] = s; pss[t] = ss;
    __syncthreads();
    if (t < 64) {
        float S  = ps[t]  + ps[t+64]  + ps[t+128]  + ps[t+192];
        float SS = pss[t] + pss[t+64] + pss[t+128] + pss[t+192];
        g_part[blockIdx.x*64 + t] = S;
        g_partsq[blockIdx.x*64 + t] = SS;
    }
}

__global__ __launch_bounds__(64) void bnfin_kernel(
    const float* __restrict__ gamma, const float* __restrict__ beta)
{
    int c = threadIdx.x;
    float s = 0.f, ss = 0.f;
    for (int p = 0; p < 256; p++) { s += g_part[p*64 + c]; ss += g_partsq[p*64 + c]; }
    const float inv = 1.f / 32768.f;
    float mean = s * inv;
    float var = ss * inv - mean*mean;
    if (var < 0.f) var = 0.f;
    float sc = gamma[c] * rsqrtf(var + 1e-5f);
    g_scale[c] = sc;
    g_shift[c] = beta[c] - mean*sc;
}

// ---------------- loss = mean((h - target)^2) ----------------
__global__ __launch_bounds__(256) void lossred_kernel(
    const float* __restrict__ h, const float* __restrict__ tgt)
{
    __shared__ float ps[256];
    int t = threadIdx.x;
    int base = blockIdx.x * 1024;
    float s = 0.f;
    for (int k = t; k < 1024; k += 256) {
        float d = h[base + k] - tgt[base + k];
        s += d*d;
    }
    ps[t] = s; __syncthreads();
    for (int off = 128; off > 0; off >>= 1) {
        if (t < off) ps[t] += ps[t + off];
        __syncthreads();
    }
    if (t == 0) g_lpart[blockIdx.x] = ps[0];
}

__global__ __launch_bounds__(128) void lossfin_kernel(float* __restrict__ out_loss)
{
    __shared__ float buf[128];
    int t = threadIdx.x;
    buf[t] = (t < 96) ? g_lpart[t] : 0.f;
    __syncthreads();
    for (int off = 64; off > 0; off >>= 1) {
        if (t < off) buf[t] += buf[t + off];
        __syncthreads();
    }
    if (t == 0) *out_loss = buf[0] / 98304.0f;
}

// ---------------- driver ----------------
extern "C" void kernel_launch(void* const* d_in, const int* in_sizes, int n_in,
                              void* d_out, int out_size)
{
    const float* x   = (const float*)d_in[0];
    const float* tgt = (const float*)d_in[1];
    const float* W1  = (const float*)d_in[2];
    const float* b1  = (const float*)d_in[3];
    const float* g1  = (const float*)d_in[4];
    const float* be1 = (const float*)d_in[5];
    const float* W2  = (const float*)d_in[6];
    const float* b2  = (const float*)d_in[7];
    const float* g2  = (const float*)d_in[8];
    const float* be2 = (const float*)d_in[9];
    const float* W3  = (const float*)d_in[10];
    const float* b3  = (const float*)d_in[11];
    float* out = (float*)d_out;

    float *p_xT, *p_sq, *p_q, *p_v, *p_y;
    cudaGetSymbolAddress((void**)&p_xT, g_xT);
    cudaGetSymbolAddress((void**)&p_sq, g_sq);
    cudaGetSymbolAddress((void**)&p_q,  g_q);
    cudaGetSymbolAddress((void**)&p_v,  g_v);
    cudaGetSymbolAddress((void**)&p_y,  g_y);

    const int smem3  = (2*3*128  + 128) * (int)sizeof(float);   //  3.5 KB
    const int smem64 = (2*64*128 + 128) * (int)sizeof(float);   // 66.0 KB
    cudaFuncSetAttribute(fused_knn_kernel<64,64>,
                         cudaFuncAttributeMaxDynamicSharedMemorySize, smem64);
    cudaFuncSetAttribute(fused_knn_kernel<64,3>,
                         cudaFuncAttributeMaxDynamicSharedMemorySize, smem64);

    // ----- layer 1 (f=3 -> 64) -----
    prep1_kernel<<<256, 128>>>(x, W1, b1);
    fused_knn_kernel<3,64><<<512, 256, smem3>>>(p_xT, p_sq, p_v, p_q, p_y);
    bnred_kernel<<<256, 256>>>();
    bnfin_kernel<<<1, 64>>>(g1, be1);

    // ----- layer 2 (f=64 -> 64) -----
    prepbn_kernel<64><<<256, 128>>>(W2, b2);
    fused_knn_kernel<64,64><<<512, 256, smem64>>>(p_xT, p_sq, p_v, p_q, p_y);
    bnred_kernel<<<256, 256>>>();
    bnfin_kernel<<<1, 64>>>(g2, be2);

    // ----- layer 3 (f=64 -> 3), h straight to d_out -----
    prepbn_kernel<3><<<256, 128>>>(W3, b3);
    fused_knn_kernel<64,3><<<512, 256, smem64>>>(p_xT, p_sq, p_v, p_q, out);

    // ----- loss -----
    lossred_kernel<<<96, 256>>>(out, tgt);
    lossfin_kernel<<<1, 128>>>(out + (out_size - 1));
}

// round 3
// speedup vs baseline: 1.6642x; 1.0432x over previous
#include <cuda_runtime.h>
#include <math.h>
#include <stdint.h>

#define NPTS 4096
#define NB 8
#define KNN 32
#define ROWS_TOTAL (NB*NPTS)   // 32768
#define FULLMASK 0xffffffffu

typedef unsigned long long u64;

// ---------------- scratch (device globals; no allocation) ----------------
__device__ float g_xT[(size_t)NB*64*NPTS];    // transposed features [b][f][n] (8MB)
__device__ float g_sq[ROWS_TOTAL];            // row squared norms
__device__ float g_q[ROWS_TOTAL*64];          // constant part per edgeconv
__device__ float g_v[ROWS_TOTAL*64];          // neighbor part per edgeconv
__device__ float g_y[ROWS_TOTAL*64];          // edgeconv output (pre ReLU+BN)
__device__ float g_scale[64];
__device__ float g_shift[64];
__device__ float g_part[256*64];
__device__ float g_partsq[256*64];
__device__ float g_lpart[96];

// packed f32x2 fma (sm_100+): 2 FMAs per instruction -> full fp32 rate
__device__ __forceinline__ u64 ffma2(u64 a, u64 b, u64 c)
{
    u64 d;
    asm("fma.rn.f32x2 %0, %1, %2, %3;" : "=l"(d) : "l"(a), "l"(b), "l"(c));
    return d;
}

__device__ __forceinline__ unsigned ordf(float f) {
    unsigned u = __float_as_uint(f);
    return u ^ (unsigned)(((int)u >> 31) | 0x80000000);
}
__device__ __forceinline__ float iordf(unsigned u) {
    unsigned v = (u & 0x80000000u) ? (u ^ 0x80000000u) : ~u;
    return __uint_as_float(v);
}

__device__ __forceinline__ void cpasync16(uint32_t dst, const void* src) {
    asm volatile("cp.async.cg.shared.global [%0], [%1], 16;" :: "r"(dst), "l"(src));
}
__device__ __forceinline__ void cp_commit() {
    asm volatile("cp.async.commit_group;");
}
template<int N>
__device__ __forceinline__ void cp_wait() {
    asm volatile("cp.async.wait_group %0;" :: "n"(N));
}

// ---------------- layer-1 prep: xT,q,v,sq from raw x (f=3) ----------------
__global__ __launch_bounds__(128) void prep1_kernel(
    const float* __restrict__ x, const float* __restrict__ W,
    const float* __restrict__ b)
{
    __shared__ float sW[6*64];
    __shared__ float sb[64];
    int t = threadIdx.x;
    for (int i = t; i < 6*64; i += 128) sW[i] = W[i];
    if (t < 64) sb[t] = b[t];
    __syncthreads();
    int row = blockIdx.x * 128 + t;
    int bt = row >> 12, n = row & 4095;
    float x0 = x[row*3+0], x1 = x[row*3+1], x2 = x[row*3+2];
    g_sq[row] = x0*x0 + x1*x1 + x2*x2;
    g_xT[((size_t)bt*3 + 0)*NPTS + n] = x0;
    g_xT[((size_t)bt*3 + 1)*NPTS + n] = x1;
    g_xT[((size_t)bt*3 + 2)*NPTS + n] = x2;
    #pragma unroll 4
    for (int o = 0; o < 64; o++) {
        float s1 = x0*sW[0*64+o] + x1*sW[1*64+o] + x2*sW[2*64+o];
        float s2 = x0*sW[3*64+o] + x1*sW[4*64+o] + x2*sW[5*64+o];
        g_q[row*64+o] = s1 - s2 + sb[o];
        g_v[row*64+o] = s2;
    }
}

// ------- layers 2/3 prep: ReLU+BN on y -> xT, sq, q, v (f=64) -------
template<int O>
__global__ __launch_bounds__(128) void prepbn_kernel(
    const float* __restrict__ W, const float* __restrict__ b)
{
    __shared__ float sW[128*O];
    __shared__ float sb[O];
    __shared__ float ssc[64], ssh[64];
    int t = threadIdx.x;
    for (int i = t; i < 128*O; i += 128) sW[i] = W[i];
    if (t < O) sb[t] = b[t];
    if (t < 64) { ssc[t] = g_scale[t]; ssh[t] = g_shift[t]; }
    __syncthreads();
    int row = blockIdx.x * 128 + t;
    int bt = row >> 12, n = row & 4095;
    float xr[64];
    float s = 0.f;
    #pragma unroll
    for (int f = 0; f < 64; f++) {
        float yy = g_y[(size_t)row*64 + f];
        float xn = ssc[f]*fmaxf(yy, 0.f) + ssh[f];
        xr[f] = xn;
        s += xn*xn;
        g_xT[((size_t)bt*64 + f)*NPTS + n] = xn;
    }
    g_sq[row] = s;
    #pragma unroll 2
    for (int o = 0; o < O; o++) {
        float s1 = 0.f, s2 = 0.f;
        #pragma unroll
        for (int f = 0; f < 64; f++) {
            s1 += xr[f]*sW[f*O + o];
            s2 += xr[f]*sW[(64+f)*O + o];
        }
        g_q[(size_t)row*O + o] = s1 - s2 + sb[o];
        g_v[(size_t)row*O + o] = s2;
    }
}

// ============= fused: dist + exact top-32 stream-select + v-gather =============
// Block: 256 threads = 8 warps; each warp owns 8 rows i; block = 64 rows.
// j streamed in chunks of 128 via double-buffered cp.async.
// Lane l owns j pairs (2l,2l+1) and (64+2l,64+2l+1)  -> conflict-free LDS.64.
// Ranking key = sq_j - 2*dot(x_i,x_j)  (monotone with true dist per row).
template<int F, int O>
__global__ __launch_bounds__(256, 2) void fused_knn_kernel(
    const float* __restrict__ XT, const float* __restrict__ SQ,
    const float* __restrict__ V, const float* __restrict__ Q,
    float* __restrict__ OUT)
{
    extern __shared__ float sm[];
    // layout (floats): xj[2][F*128] | sqj[2][128] | xi2[F*128]
    float* s_xj  = sm;
    float* s_sqj = sm + 2*F*128;
    float* s_xi2 = sm + 2*F*128 + 256;
    const uint32_t smem_b = (uint32_t)__cvta_generic_to_shared(sm);

    const int t = threadIdx.x;
    const int lane = t & 31;
    const int w = t >> 5;
    const int wrow = w * 8;
    const int rowbase = blockIdx.x * 64;
    const int batch = rowbase >> 12;
    const int nbase = rowbase & 4095;
    const float* XTb = XT + (size_t)batch * F * NPTS;
    const float* SQb = SQ + batch * NPTS;

    // build xi2 tile once: packed duplicated (-2*x_i), [f][i] as float2
    for (int idx = t; idx < F*64; idx += 256) {
        int f = idx >> 6, i = idx & 63;
        float s = -2.0f * XTb[(size_t)f * NPTS + nbase + i];
        ((float2*)s_xi2)[f*64 + i] = make_float2(s, s);
    }

    // stage chunk jb into buffer buf (async)
    auto stage = [&](int jb, int buf) {
        uint32_t xb = smem_b + (uint32_t)(buf * F * 128 * 4);
        if (F == 64) {
            #pragma unroll
            for (int r = 0; r < 8; r++) {
                int idx = t + 256*r;
                int f = idx >> 5, c = idx & 31;
                cpasync16(xb + (uint32_t)(f*512 + 16*c),
                          &XTb[(size_t)f*NPTS + jb + 4*c]);
            }
        } else {
            if (t < F*32) {
                int f = t >> 5, c = t & 31;
                cpasync16(xb + (uint32_t)(f*512 + 16*c),
                          &XTb[(size_t)f*NPTS + jb + 4*c]);
            }
        }
        if (t < 32) cpasync16(smem_b + (uint32_t)((2*F*128 + buf*128)*4 + 16*t),
                              &SQb[jb + 4*t]);
        cp_commit();
    };

    u64 acc0[8], acc1[8];
    unsigned svalu[8]; int sidx[8]; float thrf[8]; int vlane[8];
    #pragma unroll
    for (int i = 0; i < 8; i++) {
        svalu[i] = 0xFF800000u;   // ordf(+inf)
        sidx[i] = 0;
        thrf[i] = INFINITY;
        vlane[i] = 0;
    }

    stage(0, 0);

    for (int c = 0; c < 32; c++) {
        const int buf = c & 1;
        const int jb = c * 128;
        if (c < 31) { stage(jb + 128, buf ^ 1); cp_wait<1>(); }
        else        { cp_wait<0>(); }
        __syncthreads();

        const float* xjb  = s_xj + buf * F * 128;
        const float* sqjb = s_sqj + buf * 128;

        u64 sq01 = *(const u64*)(sqjb + 2*lane);
        u64 sq23 = *(const u64*)(sqjb + 64 + 2*lane);
        #pragma unroll
        for (int i = 0; i < 8; i++) { acc0[i] = sq01; acc1[i] = sq23; }

        #pragma unroll 16
        for (int f = 0; f < F; f++) {
            const float* xf = xjb + f*128;
            u64 xj01 = *(const u64*)(xf + 2*lane);
            u64 xj23 = *(const u64*)(xf + 64 + 2*lane);
            const ulonglong2* xip = (const ulonglong2*)(s_xi2 + f*128 + 2*wrow);
            ulonglong2 q0 = xip[0], q1 = xip[1], q2 = xip[2], q3 = xip[3];
            acc0[0] = ffma2(q0.x, xj01, acc0[0]); acc1[0] = ffma2(q0.x, xj23, acc1[0]);
            acc0[1] = ffma2(q0.y, xj01, acc0[1]); acc1[1] = ffma2(q0.y, xj23, acc1[1]);
            acc0[2] = ffma2(q1.x, xj01, acc0[2]); acc1[2] = ffma2(q1.x, xj23, acc1[2]);
            acc0[3] = ffma2(q1.y, xj01, acc0[3]); acc1[3] = ffma2(q1.y, xj23, acc1[3]);
            acc0[4] = ffma2(q2.x, xj01, acc0[4]); acc1[4] = ffma2(q2.x, xj23, acc1[4]);
            acc0[5] = ffma2(q2.y, xj01, acc0[5]); acc1[5] = ffma2(q2.y, xj23, acc1[5]);
            acc0[6] = ffma2(q3.x, xj01, acc0[6]); acc1[6] = ffma2(q3.x, xj23, acc1[6]);
            acc0[7] = ffma2(q3.y, xj01, acc0[7]); acc1[7] = ffma2(q3.y, xj23, acc1[7]);
        }

        // ------- gated exact streaming top-32 (float compares; ordf on insert) -------
        float rmin[8];
        bool anyp = false;
        #pragma unroll
        for (int i = 0; i < 8; i++) {
            float k0 = __uint_as_float((unsigned)acc0[i]);
            float k1 = __uint_as_float((unsigned)(acc0[i] >> 32));
            float k2 = __uint_as_float((unsigned)acc1[i]);
            float k3 = __uint_as_float((unsigned)(acc1[i] >> 32));
            rmin[i] = fminf(fminf(k0, k1), fminf(k2, k3));
            anyp |= (rmin[i] < thrf[i]);
        }
        if (__ballot_sync(FULLMASK, anyp)) {
            #pragma unroll
            for (int i = 0; i < 8; i++) {
                if (!__ballot_sync(FULLMASK, rmin[i] < thrf[i])) continue;
                #pragma unroll
                for (int s = 0; s < 4; s++) {
                    float key;
                    if (s == 0)      key = __uint_as_float((unsigned)acc0[i]);
                    else if (s == 1) key = __uint_as_float((unsigned)(acc0[i] >> 32));
                    else if (s == 2) key = __uint_as_float((unsigned)acc1[i]);
                    else             key = __uint_as_float((unsigned)(acc1[i] >> 32));
                    unsigned m = __ballot_sync(FULLMASK, key < thrf[i]);
                    while (m) {
                        int src = __ffs(m) - 1; m &= m - 1;
                        float kc = __shfl_sync(FULLMASK, key, src);
                        if (kc < thrf[i]) {
                            if (lane == vlane[i]) {
                                svalu[i] = ordf(kc);
                                sidx[i] = jb + ((s >> 1) << 6) + 2*src + (s & 1);
                            }
                            unsigned tu = __reduce_max_sync(FULLMASK, svalu[i]);
                            vlane[i] = __ffs(__ballot_sync(FULLMASK, svalu[i] == tu)) - 1;
                            thrf[i] = iordf(tu);
                        }
                    }
                }
            }
        }
        __syncthreads();
    }

    // v-gather-max + output (winners: one per lane per row)
    const int bb = batch * NPTS;
    #pragma unroll
    for (int i = 0; i < 8; i++) {
        int row = rowbase + wrow + i;
        if (O == 64) {
            float m0 = -INFINITY, m1 = -INFINITY;
            #pragma unroll 4
            for (int s = 0; s < 32; s++) {
                int js = __shfl_sync(FULLMASK, sidx[i], s);
                const float* vp = V + (size_t)(bb + js) * 64;
                m0 = fmaxf(m0, vp[lane]);
                m1 = fmaxf(m1, vp[lane + 32]);
            }
            OUT[(size_t)row*64 + lane]      = Q[(size_t)row*64 + lane] + m0;
            OUT[(size_t)row*64 + lane + 32] = Q[(size_t)row*64 + lane + 32] + m1;
        } else {
            float m0 = -INFINITY;
            for (int s = 0; s < 32; s++) {
                int js = __shfl_sync(FULLMASK, sidx[i], s);
                if (lane < O) m0 = fmaxf(m0, V[(size_t)(bb + js) * O + lane]);
            }
            if (lane < O) OUT[(size_t)row*O + lane] = Q[(size_t)row*O + lane] + m0;
        }
    }
}

// ---------------- BN stats: partial sums over ReLU(y) ----------------
__global__ __launch_bounds__(256) void bnred_kernel()
{
    __shared__ float ps[256], pss[256];
    int t = threadIdx.x, c = t & 63, g = t >> 6;
    int row0 = blockIdx.x * 128;
    float s = 0.f, ss = 0.f;
    for (int r = g; r < 128; r += 4) {
        float a = fmaxf(g_y[(size_t)(row0+r)*64 + c], 0.f);
        s += a; ss += a*a;
    }
    ps[t] = s; pss[t] = ss;
    __syncthreads();
    if (t < 64) {
        float S  = ps[t]  + ps[t+64]  + ps[t+128]  + ps[t+192];
        float SS = pss[t] + pss[t+64] + pss[t+128] + pss[t+192];
        g_part[blockIdx.x*64 + t] = S;
        g_partsq[blockIdx.x*64 + t] = SS;
    }
}

__global__ __launch_bounds__(256) void bnfin_kernel(
    const float* __restrict__ gamma, const float* __restrict__ beta)
{
    __shared__ float s1[256], s2[256];
    int t = threadIdx.x, c = t & 63, g = t >> 6;
    float s = 0.f, ss = 0.f;
    for (int p = g; p < 256; p += 4) {
        s += g_part[p*64 + c]; ss += g_partsq[p*64 + c];
    }
    s1[t] = s; s2[t] = ss;
    __syncthreads();
    if (t < 64) {
        float S  = s1[t] + s1[t+64] + s1[t+128] + s1[t+192];
        float SS = s2[t] + s2[t+64] + s2[t+128] + s2[t+192];
        const float inv = 1.f / 32768.f;
        float mean = S * inv;
        float var = SS * inv - mean*mean;
        if (var < 0.f) var = 0.f;
        float sc = gamma[t] * rsqrtf(var + 1e-5f);
        g_scale[t] = sc;
        g_shift[t] = beta[t] - mean*sc;
    }
}

// ---------------- loss = mean((h - target)^2) ----------------
__global__ __launch_bounds__(256) void lossred_kernel(
    const float* __restrict__ h, const float* __restrict__ tgt)
{
    __shared__ float ps[256];
    int t = threadIdx.x;
    int base = blockIdx.x * 1024;
    float s = 0.f;
    for (int k = t; k < 1024; k += 256) {
        float d = h[base + k] - tgt[base + k];
        s += d*d;
    }
    ps[t] = s; __syncthreads();
    for (int off = 128; off > 0; off >>= 1) {
        if (t < off) ps[t] += ps[t + off];
        __syncthreads();
    }
    if (t == 0) g_lpart[blockIdx.x] = ps[0];
}

__global__ __launch_bounds__(128) void lossfin_kernel(float* __restrict__ out_loss)
{
    __shared__ float buf[128];
    int t = threadIdx.x;
    buf[t] = (t < 96) ? g_lpart[t] : 0.f;
    __syncthreads();
    for (int off = 64; off > 0; off >>= 1) {
        if (t < off) buf[t] += buf[t + off];
        __syncthreads();
    }
    if (t == 0) *out_loss = buf[0] / 98304.0f;
}

// ---------------- driver ----------------
extern "C" void kernel_launch(void* const* d_in, const int* in_sizes, int n_in,
                              void* d_out, int out_size)
{
    const float* x   = (const float*)d_in[0];
    const float* tgt = (const float*)d_in[1];
    const float* W1  = (const float*)d_in[2];
    const float* b1  = (const float*)d_in[3];
    const float* g1  = (const float*)d_in[4];
    const float* be1 = (const float*)d_in[5];
    const float* W2  = (const float*)d_in[6];
    const float* b2  = (const float*)d_in[7];
    const float* g2  = (const float*)d_in[8];
    const float* be2 = (const float*)d_in[9];
    const float* W3  = (const float*)d_in[10];
    const float* b3  = (const float*)d_in[11];
    float* out = (float*)d_out;

    float *p_xT, *p_sq, *p_q, *p_v, *p_y;
    cudaGetSymbolAddress((void**)&p_xT, g_xT);
    cudaGetSymbolAddress((void**)&p_sq, g_sq);
    cudaGetSymbolAddress((void**)&p_q,  g_q);
    cudaGetSymbolAddress((void**)&p_v,  g_v);
    cudaGetSymbolAddress((void**)&p_y,  g_y);

    const int smem3  = (2*3*128  + 256 + 3*128)  * (int)sizeof(float);  //  5.5 KB
    const int smem64 = (2*64*128 + 256 + 64*128) * (int)sizeof(float);  // 97.0 KB
    cudaFuncSetAttribute(fused_knn_kernel<64,64>,
                         cudaFuncAttributeMaxDynamicSharedMemorySize, smem64);
    cudaFuncSetAttribute(fused_knn_kernel<64,3>,
                         cudaFuncAttributeMaxDynamicSharedMemorySize, smem64);

    // ----- layer 1 (f=3 -> 64) -----
    prep1_kernel<<<256, 128>>>(x, W1, b1);
    fused_knn_kernel<3,64><<<512, 256, smem3>>>(p_xT, p_sq, p_v, p_q, p_y);
    bnred_kernel<<<256, 256>>>();
    bnfin_kernel<<<1, 256>>>(g1, be1);

    // ----- layer 2 (f=64 -> 64) -----
    prepbn_kernel<64><<<256, 128>>>(W2, b2);
    fused_knn_kernel<64,64><<<512, 256, smem64>>>(p_xT, p_sq, p_v, p_q, p_y);
    bnred_kernel<<<256, 256>>>();
    bnfin_kernel<<<1, 256>>>(g2, be2);

    // ----- layer 3 (f=64 -> 3), h straight to d_out -----
    prepbn_kernel<3><<<256, 128>>>(W3, b3);
    fused_knn_kernel<64,3><<<512, 256, smem64>>>(p_xT, p_sq, p_v, p_q, out);

    // ----- loss -----
    lossred_kernel<<<96, 256>>>(out, tgt);
    lossfin_kernel<<<1, 128>>>(out + (out_size - 1));
}